// round 1
// baseline (speedup 1.0000x reference)
#include <cuda_runtime.h>

// Problem constants (fixed-shape problem)
#define NN 100000
#define DD 64
#define D2 (DD/2)          // float2 elements per row
#define EE 1600000
#define DTC 0.2f

// ---------------- scratch (device globals: no runtime allocation) ------------
__device__ int   g_deg_r[NN];
__device__ int   g_deg_c[NN];
__device__ int   g_start[NN];
__device__ int   g_fill[NN];
__device__ float g_dinv_r[NN];
__device__ float g_dinv_c[NN];
__device__ int   g_cursor;
__device__ int2  g_e1[EE];      // {col, w * mask[col]}   (hop 1)
__device__ int2  g_e2[EE];      // {col, -w}              (hop 2, folds -ETA)
__device__ float g_tmp[NN*DD];  // hop-1 output
__device__ float g_k[NN*DD];    // current stage k
__device__ float g_acc[NN*DD];  // k1 + 2k2 + 2k3
__device__ float g_y[NN*DD];    // stage input r + c*k

// ---------------- CSR build --------------------------------------------------
__global__ void k_zero() {
    int i = blockIdx.x * blockDim.x + threadIdx.x;
    if (i < NN) { g_deg_r[i] = 0; g_deg_c[i] = 0; }
    if (i == 0) g_cursor = 0;
}

__global__ void k_count(const int* __restrict__ row, const int* __restrict__ col) {
    int e = blockIdx.x * blockDim.x + threadIdx.x;
    if (e < EE) {
        atomicAdd(&g_deg_r[row[e]], 1);
        atomicAdd(&g_deg_c[col[e]], 1);
    }
}

// Warp-aggregated segment assignment: one atomicAdd per warp on the global
// cursor instead of one per node (avoids single-address atomic serialization).
__global__ void k_start() {
    int i = blockIdx.x * blockDim.x + threadIdx.x;
    int lane = threadIdx.x & 31;
    int deg = (i < NN) ? g_deg_r[i] : 0;
    // inclusive warp scan of deg
    int s = deg;
    #pragma unroll
    for (int o = 1; o < 32; o <<= 1) {
        int t = __shfl_up_sync(0xFFFFFFFFu, s, o);
        if (lane >= o) s += t;
    }
    int total = __shfl_sync(0xFFFFFFFFu, s, 31);
    int base = 0;
    if (lane == 31) base = atomicAdd(&g_cursor, total);
    base = __shfl_sync(0xFFFFFFFFu, base, 31);
    int start = base + s - deg;   // exclusive
    if (i < NN) {
        g_start[i] = start;
        g_fill[i]  = start;
        g_dinv_r[i] = (deg > 0) ? rsqrtf((float)deg) : 0.f;
        int dc = g_deg_c[i];
        g_dinv_c[i] = (dc > 0) ? rsqrtf((float)dc) : 0.f;
    }
}

__global__ void k_fill(const int* __restrict__ row, const int* __restrict__ col,
                       const int* __restrict__ mask) {
    int e = blockIdx.x * blockDim.x + threadIdx.x;
    if (e < EE) {
        int r = row[e], c = col[e];
        int p = atomicAdd(&g_fill[r], 1);
        float w = g_dinv_r[r] * g_dinv_c[c];
        g_e1[p] = make_int2(c, __float_as_int(w * (float)mask[c]));
        g_e2[p] = make_int2(c, __float_as_int(-w));
    }
}

// ---------------- stage-input AXPY: y = r + c*k ------------------------------
__global__ void k_axpy(const float4* __restrict__ r, float c) {
    int i = blockIdx.x * blockDim.x + threadIdx.x;
    if (i < NN * DD / 4) {
        float4 a = r[i];
        float4 b = ((const float4*)g_k)[i];
        ((float4*)g_y)[i] = make_float4(a.x + c * b.x, a.y + c * b.y,
                                        a.z + c * b.z, a.w + c * b.w);
    }
}

// ---------------- SpMM: warp per row, lane = 2 features ----------------------
// MODE: 0 = hop1 PLAIN (edges e1, out = g_tmp, x = xp or g_y)
//       1 = hop2 INIT  (edges e2, x = g_tmp, out = g_k, acc = k)
//       2 = hop2 ACC   (edges e2, x = g_tmp, out = g_k, acc += 2k)
//       3 = hop2 FINAL (edges e2, x = g_tmp, out = rn = r + DT/6*(acc+k))
#define M_PLAIN 0
#define M_INIT  1
#define M_ACC   2
#define M_FINAL 3

template<int MODE, bool SRC_Y>
__global__ void __launch_bounds__(256)
k_spmm(const float2* __restrict__ xp, float2* __restrict__ outp,
       const float2* __restrict__ rr) {
    int w = (blockIdx.x * blockDim.x + threadIdx.x) >> 5;
    if (w >= NN) return;
    int lane = threadIdx.x & 31;

    const float2* x = SRC_Y ? (const float2*)g_y
                            : (MODE == M_PLAIN ? xp : (const float2*)g_tmp);
    const int2* ed = (MODE == M_PLAIN) ? g_e1 : g_e2;

    int start = g_start[w];
    int deg   = g_deg_r[w];
    const int2* ep = ed + start;

    float sx = 0.f, sy = 0.f;
    int e = 0;
    int deg4 = deg & ~3;
    for (; e < deg4; e += 4) {
        int2 m0 = __ldg(ep + e);
        int2 m1 = __ldg(ep + e + 1);
        int2 m2 = __ldg(ep + e + 2);
        int2 m3 = __ldg(ep + e + 3);
        float2 v0 = __ldg(x + m0.x * D2 + lane);
        float2 v1 = __ldg(x + m1.x * D2 + lane);
        float2 v2 = __ldg(x + m2.x * D2 + lane);
        float2 v3 = __ldg(x + m3.x * D2 + lane);
        float w0 = __int_as_float(m0.y);
        float w1 = __int_as_float(m1.y);
        float w2 = __int_as_float(m2.y);
        float w3 = __int_as_float(m3.y);
        sx = fmaf(w0, v0.x, sx); sy = fmaf(w0, v0.y, sy);
        sx = fmaf(w1, v1.x, sx); sy = fmaf(w1, v1.y, sy);
        sx = fmaf(w2, v2.x, sx); sy = fmaf(w2, v2.y, sy);
        sx = fmaf(w3, v3.x, sx); sy = fmaf(w3, v3.y, sy);
    }
    for (; e < deg; e++) {
        int2 m = __ldg(ep + e);
        float2 v = __ldg(x + m.x * D2 + lane);
        float wf = __int_as_float(m.y);
        sx = fmaf(wf, v.x, sx); sy = fmaf(wf, v.y, sy);
    }

    int idx = w * D2 + lane;
    if (MODE == M_PLAIN) {
        ((float2*)g_tmp)[idx] = make_float2(sx, sy);
    } else if (MODE == M_INIT) {
        ((float2*)g_k)[idx]   = make_float2(sx, sy);
        ((float2*)g_acc)[idx] = make_float2(sx, sy);
    } else if (MODE == M_ACC) {
        ((float2*)g_k)[idx] = make_float2(sx, sy);
        float2 a = ((float2*)g_acc)[idx];
        a.x = fmaf(2.f, sx, a.x);
        a.y = fmaf(2.f, sy, a.y);
        ((float2*)g_acc)[idx] = a;
    } else { // M_FINAL
        float2 a = ((float2*)g_acc)[idx];
        float2 rv = __ldg(rr + idx);
        const float f = DTC / 6.f;
        outp[idx] = make_float2(rv.x + f * (a.x + sx),
                                rv.y + f * (a.y + sy));
    }
}

// ---------------- launcher ---------------------------------------------------
extern "C" void kernel_launch(void* const* d_in, const int* in_sizes, int n_in,
                              void* d_out, int out_size) {
    const float* r0  = (const float*)d_in[0];
    const int*   ei  = (const int*)d_in[1];
    const int*   msk = (const int*)d_in[2];
    const int* row = ei;
    const int* col = ei + EE;
    float* out = (float*)d_out;
    const size_t nd = (size_t)NN * DD;

    // out[0] = r0
    cudaMemcpyAsync(out, r0, nd * sizeof(float), cudaMemcpyDeviceToDevice);

    // CSR build (runs every replay; ~tens of us)
    k_zero <<<(NN + 255) / 256, 256>>>();
    k_count<<<(EE + 255) / 256, 256>>>(row, col);
    k_start<<<(NN + 255) / 256, 256>>>();
    k_fill <<<(EE + 255) / 256, 256>>>(row, col, msk);

    const int SPMM_BLOCKS = (NN + 7) / 8;       // 8 warps / block of 256
    const int AXPY_BLOCKS = (NN * DD / 4 + 255) / 256;

    for (int s = 0; s < 5; s++) {
        const float2* r  = (const float2*)(out + (size_t)s * nd);
        float2*       rn = (float2*)(out + (size_t)(s + 1) * nd);

        // stage 1: k1 = f(r)
        k_spmm<M_PLAIN, false><<<SPMM_BLOCKS, 256>>>(r, nullptr, nullptr);
        k_spmm<M_INIT,  false><<<SPMM_BLOCKS, 256>>>(nullptr, nullptr, nullptr);

        // stage 2: k2 = f(r + 0.5*DT*k1)
        k_axpy<<<AXPY_BLOCKS, 256>>>((const float4*)r, 0.5f * DTC);
        k_spmm<M_PLAIN, true ><<<SPMM_BLOCKS, 256>>>(nullptr, nullptr, nullptr);
        k_spmm<M_ACC,   false><<<SPMM_BLOCKS, 256>>>(nullptr, nullptr, nullptr);

        // stage 3: k3 = f(r + 0.5*DT*k2)
        k_axpy<<<AXPY_BLOCKS, 256>>>((const float4*)r, 0.5f * DTC);
        k_spmm<M_PLAIN, true ><<<SPMM_BLOCKS, 256>>>(nullptr, nullptr, nullptr);
        k_spmm<M_ACC,   false><<<SPMM_BLOCKS, 256>>>(nullptr, nullptr, nullptr);

        // stage 4: k4 = f(r + DT*k3); rn = r + DT/6*(acc + k4)
        k_axpy<<<AXPY_BLOCKS, 256>>>((const float4*)r, DTC);
        k_spmm<M_PLAIN, true ><<<SPMM_BLOCKS, 256>>>(nullptr, nullptr, nullptr);
        k_spmm<M_FINAL, false><<<SPMM_BLOCKS, 256>>>(nullptr, rn, (const float2*)r);
    }
}

// round 3
// speedup vs baseline: 1.2104x; 1.2104x over previous
#include <cuda_runtime.h>
#include <cuda_fp16.h>

// Problem constants (fixed-shape problem)
#define NN 100000
#define DD 64
#define D2 32              // half2/float2 elements per row (DD/2)
#define EE 1600000
#define DTC 0.2f

// ---------------- scratch (device globals: no runtime allocation) ------------
__device__ int     g_deg_r[NN];
__device__ int     g_deg_c[NN];
__device__ int     g_start[NN];
__device__ int     g_fill[NN];
__device__ float   g_dinv_r[NN];
__device__ float   g_dinv_c[NN];
__device__ float   g_maskf[NN];
__device__ int     g_cursor;
__device__ int2    g_edge[EE];       // {col, fp32 w = dinv_r*dinv_c}
__device__ __half2 g_yh[NN * D2];    // masked stage input (fp16)
__device__ __half2 g_th[NN * D2];    // hop-1 output (fp16)
__device__ float2  g_acc[NN * D2];   // k1 + 2k2 + 2k3 (fp32)

// ---------------- CSR build --------------------------------------------------
__global__ void k_zero() {
    int i = blockIdx.x * blockDim.x + threadIdx.x;
    if (i < NN) { g_deg_r[i] = 0; g_deg_c[i] = 0; }
    if (i == 0) g_cursor = 0;
}

__global__ void k_count(const int* __restrict__ row, const int* __restrict__ col) {
    int e = blockIdx.x * blockDim.x + threadIdx.x;
    if (e < EE) {
        atomicAdd(&g_deg_r[row[e]], 1);
        atomicAdd(&g_deg_c[col[e]], 1);
    }
}

// Warp-aggregated segment assignment (one cursor atomic per warp) + per-node
// normalization factors + float mask image.
__global__ void k_start(const int* __restrict__ mask) {
    int i = blockIdx.x * blockDim.x + threadIdx.x;
    int lane = threadIdx.x & 31;
    int deg = (i < NN) ? g_deg_r[i] : 0;
    int s = deg;
    #pragma unroll
    for (int o = 1; o < 32; o <<= 1) {
        int t = __shfl_up_sync(0xFFFFFFFFu, s, o);
        if (lane >= o) s += t;
    }
    int total = __shfl_sync(0xFFFFFFFFu, s, 31);
    int base = 0;
    if (lane == 31) base = atomicAdd(&g_cursor, total);
    base = __shfl_sync(0xFFFFFFFFu, base, 31);
    int start = base + s - deg;
    if (i < NN) {
        g_start[i] = start;
        g_fill[i]  = start;
        g_dinv_r[i] = (deg > 0) ? rsqrtf((float)deg) : 0.f;
        int dc = g_deg_c[i];
        g_dinv_c[i] = (dc > 0) ? rsqrtf((float)dc) : 0.f;
        g_maskf[i] = (float)mask[i];
    }
}

__global__ void k_fill(const int* __restrict__ row, const int* __restrict__ col) {
    int e = blockIdx.x * blockDim.x + threadIdx.x;
    if (e < EE) {
        int r = row[e], c = col[e];
        int p = atomicAdd(&g_fill[r], 1);
        float w = g_dinv_r[r] * g_dinv_c[c];
        g_edge[p] = make_int2(c, __float_as_int(w));
    }
}

// Initial masked fp16 image of r0
__global__ void k_prep(const float2* __restrict__ r0) {
    int i = blockIdx.x * blockDim.x + threadIdx.x;
    if (i < NN * D2) {
        float mf = g_maskf[i >> 5];
        float2 v = r0[i];
        g_yh[i] = __float22half2_rn(make_float2(mf * v.x, mf * v.y));
    }
}

// ---------------- SpMM: warp per row, lane = 2 features (fp16 gather) --------
// MODE H1:    tmp = A * y_h                       (write g_th fp16)
// MODE INIT:  k = -A*tmp; acc = k;   y_h = fp16(mask*(r + c*k))
// MODE ACC:   k = -A*tmp; acc += 2k; y_h = fp16(mask*(r + c*k))
// MODE FINAL: k = -A*tmp; rn = r + DT/6*(acc+k); y_h = fp16(mask*rn)
#define M_H1    0
#define M_INIT  1
#define M_ACC   2
#define M_FINAL 3

template<int MODE>
__global__ void __launch_bounds__(256)
k_spmm(float2* __restrict__ outr, const float2* __restrict__ rr, float c) {
    int w = (blockIdx.x * blockDim.x + threadIdx.x) >> 5;
    if (w >= NN) return;
    int lane = threadIdx.x & 31;

    const __half2* x = (MODE == M_H1) ? g_yh : g_th;
    int start = g_start[w];
    int deg   = g_deg_r[w];
    const int2* ep = g_edge + start;

    float sx = 0.f, sy = 0.f;
    int e = 0;
    int deg4 = deg & ~3;
    for (; e < deg4; e += 4) {
        int2 m0 = __ldg(ep + e);
        int2 m1 = __ldg(ep + e + 1);
        int2 m2 = __ldg(ep + e + 2);
        int2 m3 = __ldg(ep + e + 3);
        __half2 h0 = __ldg(x + m0.x * D2 + lane);
        __half2 h1 = __ldg(x + m1.x * D2 + lane);
        __half2 h2 = __ldg(x + m2.x * D2 + lane);
        __half2 h3 = __ldg(x + m3.x * D2 + lane);
        float w0 = __int_as_float(m0.y);
        float w1 = __int_as_float(m1.y);
        float w2 = __int_as_float(m2.y);
        float w3 = __int_as_float(m3.y);
        float2 v0 = __half22float2(h0);
        float2 v1 = __half22float2(h1);
        float2 v2 = __half22float2(h2);
        float2 v3 = __half22float2(h3);
        sx = fmaf(w0, v0.x, sx); sy = fmaf(w0, v0.y, sy);
        sx = fmaf(w1, v1.x, sx); sy = fmaf(w1, v1.y, sy);
        sx = fmaf(w2, v2.x, sx); sy = fmaf(w2, v2.y, sy);
        sx = fmaf(w3, v3.x, sx); sy = fmaf(w3, v3.y, sy);
    }
    for (; e < deg; e++) {
        int2 m = __ldg(ep + e);
        __half2 h = __ldg(x + m.x * D2 + lane);
        float wf = __int_as_float(m.y);
        float2 v = __half22float2(h);
        sx = fmaf(wf, v.x, sx); sy = fmaf(wf, v.y, sy);
    }

    int idx = w * D2 + lane;
    if (MODE == M_H1) {
        g_th[idx] = __float22half2_rn(make_float2(sx, sy));
    } else {
        float kx = -sx, ky = -sy;            // fold -ETA
        if (MODE == M_FINAL) {
            float2 a  = g_acc[idx];
            float2 rv = __ldg(rr + idx);
            const float f = DTC / 6.f;
            float nx = rv.x + f * (a.x + kx);
            float ny = rv.y + f * (a.y + ky);
            outr[idx] = make_float2(nx, ny);
            float mf = g_maskf[w];
            g_yh[idx] = __float22half2_rn(make_float2(mf * nx, mf * ny));
        } else {
            if (MODE == M_INIT) {
                g_acc[idx] = make_float2(kx, ky);
            } else {
                float2 a = g_acc[idx];
                a.x = fmaf(2.f, kx, a.x);
                a.y = fmaf(2.f, ky, a.y);
                g_acc[idx] = a;
            }
            float2 rv = __ldg(rr + idx);
            float mf = g_maskf[w];
            float yx = mf * fmaf(c, kx, rv.x);
            float yy = mf * fmaf(c, ky, rv.y);
            g_yh[idx] = __float22half2_rn(make_float2(yx, yy));
        }
    }
}

// ---------------- launcher ---------------------------------------------------
extern "C" void kernel_launch(void* const* d_in, const int* in_sizes, int n_in,
                              void* d_out, int out_size) {
    const float* r0  = (const float*)d_in[0];
    const int*   ei  = (const int*)d_in[1];
    const int*   msk = (const int*)d_in[2];
    const int* row = ei;
    const int* col = ei + EE;
    float* out = (float*)d_out;
    const size_t nd = (size_t)NN * DD;

    cudaMemcpyAsync(out, r0, nd * sizeof(float), cudaMemcpyDeviceToDevice);

    // CSR build + fp16 prep (runs every replay, ~100us total)
    k_zero <<<(NN + 255) / 256, 256>>>();
    k_count<<<(EE + 255) / 256, 256>>>(row, col);
    k_start<<<(NN + 255) / 256, 256>>>(msk);
    k_fill <<<(EE + 255) / 256, 256>>>(row, col);
    k_prep <<<(NN * D2 + 255) / 256, 256>>>((const float2*)r0);

    const int B = (NN + 7) / 8;     // 8 warps of 32 per 256-thread block

    for (int s = 0; s < 5; s++) {
        const float2* r  = (const float2*)(out + (size_t)s * nd);
        float2*       rn = (float2*)(out + (size_t)(s + 1) * nd);

        // stage 1
        k_spmm<M_H1>   <<<B, 256>>>(nullptr, nullptr, 0.f);
        k_spmm<M_INIT> <<<B, 256>>>(nullptr, r, 0.5f * DTC);
        // stage 2
        k_spmm<M_H1>   <<<B, 256>>>(nullptr, nullptr, 0.f);
        k_spmm<M_ACC>  <<<B, 256>>>(nullptr, r, 0.5f * DTC);
        // stage 3
        k_spmm<M_H1>   <<<B, 256>>>(nullptr, nullptr, 0.f);
        k_spmm<M_ACC>  <<<B, 256>>>(nullptr, r, DTC);
        // stage 4
        k_spmm<M_H1>   <<<B, 256>>>(nullptr, nullptr, 0.f);
        k_spmm<M_FINAL><<<B, 256>>>(rn, r, 0.f);
    }
}

// round 4
// speedup vs baseline: 1.2958x; 1.0706x over previous
#include <cuda_runtime.h>
#include <cuda_fp16.h>

// Problem constants (fixed-shape problem)
#define NN 100000
#define DD 64
#define D2 32              // half2 elements per row
#define EE 1600000
#define DTC 0.2f

// ---------------- scratch (device globals: no runtime allocation) ------------
__device__ int     g_deg_r[NN];
__device__ int     g_deg_c[NN];
__device__ int     g_start[NN];
__device__ int     g_fill[NN];
__device__ float   g_dinv_r[NN];
__device__ float   g_dinv_c[NN];
__device__ float   g_maskf[NN];
__device__ int     g_cursor;
__device__ int2    g_edge[EE];        // {col, fp32 w = dinv_r*dinv_c}
__device__ __half2 g_yh[NN * D2];     // masked stage input (fp16)
__device__ __half2 g_th[NN * D2];     // hop-1 output (fp16)
__device__ float   g_accf[NN * DD];   // k1 + 2k2 + 2k3 (fp32)

// ---------------- CSR build --------------------------------------------------
__global__ void k_zero() {
    int i = blockIdx.x * blockDim.x + threadIdx.x;
    if (i < NN) { g_deg_r[i] = 0; g_deg_c[i] = 0; }
    if (i == 0) g_cursor = 0;
}

__global__ void k_count(const int* __restrict__ row, const int* __restrict__ col) {
    int e = blockIdx.x * blockDim.x + threadIdx.x;
    if (e < EE) {
        atomicAdd(&g_deg_r[row[e]], 1);
        atomicAdd(&g_deg_c[col[e]], 1);
    }
}

// Warp-aggregated segment assignment (one cursor atomic per warp) + per-node
// normalization factors + float mask image.
__global__ void k_start(const int* __restrict__ mask) {
    int i = blockIdx.x * blockDim.x + threadIdx.x;
    int lane = threadIdx.x & 31;
    int deg = (i < NN) ? g_deg_r[i] : 0;
    int s = deg;
    #pragma unroll
    for (int o = 1; o < 32; o <<= 1) {
        int t = __shfl_up_sync(0xFFFFFFFFu, s, o);
        if (lane >= o) s += t;
    }
    int total = __shfl_sync(0xFFFFFFFFu, s, 31);
    int base = 0;
    if (lane == 31) base = atomicAdd(&g_cursor, total);
    base = __shfl_sync(0xFFFFFFFFu, base, 31);
    int start = base + s - deg;
    if (i < NN) {
        g_start[i] = start;
        g_fill[i]  = start;
        g_dinv_r[i] = (deg > 0) ? rsqrtf((float)deg) : 0.f;
        int dc = g_deg_c[i];
        g_dinv_c[i] = (dc > 0) ? rsqrtf((float)dc) : 0.f;
        g_maskf[i] = (float)mask[i];
    }
}

__global__ void k_fill(const int* __restrict__ row, const int* __restrict__ col) {
    int e = blockIdx.x * blockDim.x + threadIdx.x;
    if (e < EE) {
        int r = row[e], c = col[e];
        int p = atomicAdd(&g_fill[r], 1);
        float w = g_dinv_r[r] * g_dinv_c[c];
        g_edge[p] = make_int2(c, __float_as_int(w));
    }
}

// Initial masked fp16 image of r0
__global__ void k_prep(const float2* __restrict__ r0) {
    int i = blockIdx.x * blockDim.x + threadIdx.x;
    if (i < NN * D2) {
        float mf = g_maskf[i >> 5];
        float2 v = r0[i];
        g_yh[i] = __float22half2_rn(make_float2(mf * v.x, mf * v.y));
    }
}

// ---------------- SpMM -------------------------------------------------------
// Warp per row. Quarter-warp per edge: lanes split as q = lane>>3 (edge slot),
// fl = lane&7 (feature slot: 8 fp16 features = one float4). One LDG.128 per
// warp gathers 4 edges' rows; edge records are loaded 32-wide and broadcast
// via shfl (1/32 LDG per edge).
//
// MODE H1:    tmp = A * y_h                       (write g_th fp16)
// MODE INIT:  k = -A*tmp; acc = k;   y_h = fp16(mask*(r + c*k))
// MODE ACC:   k = -A*tmp; acc += 2k; y_h = fp16(mask*(r + c*k))
// MODE FINAL: k = -A*tmp; rn = r + DT/6*(acc+k); y_h = fp16(mask*rn)
#define M_H1    0
#define M_INIT  1
#define M_ACC   2
#define M_FINAL 3

__device__ __forceinline__ uint4 pack8h(const float* v) {
    union { __half2 h[4]; uint4 u; } p;
    p.h[0] = __floats2half2_rn(v[0], v[1]);
    p.h[1] = __floats2half2_rn(v[2], v[3]);
    p.h[2] = __floats2half2_rn(v[4], v[5]);
    p.h[3] = __floats2half2_rn(v[6], v[7]);
    return p.u;
}

template<int MODE>
__global__ void __launch_bounds__(256)
k_spmm(float4* __restrict__ outr, const float4* __restrict__ rr, float c) {
    int w = (blockIdx.x * blockDim.x + threadIdx.x) >> 5;
    if (w >= NN) return;
    int lane = threadIdx.x & 31;
    int q  = lane >> 3;      // edge slot within group of 4
    int fl = lane & 7;       // feature slot (8 fp16 features)

    const float4* x = (const float4*)((MODE == M_H1) ? g_yh : g_th); // 8 float4/row
    int start = g_start[w];
    int deg   = g_deg_r[w];
    const int2* ep = g_edge + start;

    float acc[8];
    #pragma unroll
    for (int t = 0; t < 8; t++) acc[t] = 0.f;

    for (int base = 0; base < deg; base += 32) {
        int rem = deg - base;
        int nE = rem < 32 ? rem : 32;
        int2 my = (lane < nE) ? __ldg(ep + base + lane) : make_int2(0, 0);
        for (int j = 0; j < nE; j += 4) {
            int src = j + q;                         // <= 31 always
            int   col = __shfl_sync(0xFFFFFFFFu, my.x, src);
            float wgt = __int_as_float(__shfl_sync(0xFFFFFFFFu, my.y, src));
            float4 hv = __ldg(x + col * 8 + fl);     // 16B of this edge's row
            const __half2* hp = (const __half2*)&hv;
            #pragma unroll
            for (int t = 0; t < 4; t++) {
                float2 v = __half22float2(hp[t]);
                acc[2*t]   = fmaf(wgt, v.x, acc[2*t]);
                acc[2*t+1] = fmaf(wgt, v.y, acc[2*t+1]);
            }
        }
    }
    // reduce across the 4 quarter-warps (lanes fl, fl+8, fl+16, fl+24)
    #pragma unroll
    for (int t = 0; t < 8; t++) {
        acc[t] += __shfl_xor_sync(0xFFFFFFFFu, acc[t], 8);
        acc[t] += __shfl_xor_sync(0xFFFFFFFFu, acc[t], 16);
    }
    if (q != 0) return;      // 8 lanes carry the full row (features fl*8..fl*8+7)

    int i16 = w * 16 + fl * 2;   // float4 index into [NN*DD] float arrays
    int i8  = w * 8 + fl;        // uint4 index into fp16 row images

    if (MODE == M_H1) {
        ((uint4*)g_th)[i8] = pack8h(acc);
    } else {
        float kx[8];
        #pragma unroll
        for (int t = 0; t < 8; t++) kx[t] = -acc[t];   // fold -ETA
        float4 r1 = __ldg(rr + i16);
        float4 r2 = __ldg(rr + i16 + 1);
        const float* rv = (const float*)&r1;           // r1,r2 adjacent on stack
        float rr8[8] = { r1.x, r1.y, r1.z, r1.w, r2.x, r2.y, r2.z, r2.w };
        (void)rv;
        float mf = g_maskf[w];
        float4* accp = (float4*)g_accf;

        if (MODE == M_FINAL) {
            float4 a1 = accp[i16], a2 = accp[i16 + 1];
            float a8[8] = { a1.x, a1.y, a1.z, a1.w, a2.x, a2.y, a2.z, a2.w };
            const float f = DTC / 6.f;
            float n8[8], y8[8];
            #pragma unroll
            for (int t = 0; t < 8; t++) {
                n8[t] = rr8[t] + f * (a8[t] + kx[t]);
                y8[t] = mf * n8[t];
            }
            outr[i16]     = make_float4(n8[0], n8[1], n8[2], n8[3]);
            outr[i16 + 1] = make_float4(n8[4], n8[5], n8[6], n8[7]);
            ((uint4*)g_yh)[i8] = pack8h(y8);
        } else {
            float a8[8];
            if (MODE == M_INIT) {
                #pragma unroll
                for (int t = 0; t < 8; t++) a8[t] = kx[t];
            } else {
                float4 a1 = accp[i16], a2 = accp[i16 + 1];
                float ld[8] = { a1.x, a1.y, a1.z, a1.w, a2.x, a2.y, a2.z, a2.w };
                #pragma unroll
                for (int t = 0; t < 8; t++) a8[t] = fmaf(2.f, kx[t], ld[t]);
            }
            accp[i16]     = make_float4(a8[0], a8[1], a8[2], a8[3]);
            accp[i16 + 1] = make_float4(a8[4], a8[5], a8[6], a8[7]);
            float y8[8];
            #pragma unroll
            for (int t = 0; t < 8; t++) y8[t] = mf * fmaf(c, kx[t], rr8[t]);
            ((uint4*)g_yh)[i8] = pack8h(y8);
        }
    }
}

// ---------------- launcher ---------------------------------------------------
extern "C" void kernel_launch(void* const* d_in, const int* in_sizes, int n_in,
                              void* d_out, int out_size) {
    const float* r0  = (const float*)d_in[0];
    const int*   ei  = (const int*)d_in[1];
    const int*   msk = (const int*)d_in[2];
    const int* row = ei;
    const int* col = ei + EE;
    float* out = (float*)d_out;
    const size_t nd = (size_t)NN * DD;

    cudaMemcpyAsync(out, r0, nd * sizeof(float), cudaMemcpyDeviceToDevice);

    k_zero <<<(NN + 255) / 256, 256>>>();
    k_count<<<(EE + 255) / 256, 256>>>(row, col);
    k_start<<<(NN + 255) / 256, 256>>>(msk);
    k_fill <<<(EE + 255) / 256, 256>>>(row, col);
    k_prep <<<(NN * D2 + 255) / 256, 256>>>((const float2*)r0);

    const int B = (NN + 7) / 8;     // 8 warps of 32 per 256-thread block

    for (int s = 0; s < 5; s++) {
        const float4* r  = (const float4*)(out + (size_t)s * nd);
        float4*       rn = (float4*)(out + (size_t)(s + 1) * nd);

        // stage 1
        k_spmm<M_H1>   <<<B, 256>>>(nullptr, nullptr, 0.f);
        k_spmm<M_INIT> <<<B, 256>>>(nullptr, r, 0.5f * DTC);
        // stage 2
        k_spmm<M_H1>   <<<B, 256>>>(nullptr, nullptr, 0.f);
        k_spmm<M_ACC>  <<<B, 256>>>(nullptr, r, 0.5f * DTC);
        // stage 3
        k_spmm<M_H1>   <<<B, 256>>>(nullptr, nullptr, 0.f);
        k_spmm<M_ACC>  <<<B, 256>>>(nullptr, r, DTC);
        // stage 4
        k_spmm<M_H1>   <<<B, 256>>>(nullptr, nullptr, 0.f);
        k_spmm<M_FINAL><<<B, 256>>>(rn, r, 0.f);
    }
}